// round 9
// baseline (speedup 1.0000x reference)
#include <cuda_runtime.h>
#include <cuda_bf16.h>
#include <math.h>
#include <stdint.h>

// Problem constants
#define B_ 128
#define T_ 512
#define I_ 256
#define H_ 1024
#define O_ 256

#define NB   128      // persistent grid: 4 M-tiles x 32 N-tiles
#define NTHR 256      // 8 warps per CTA (2 per SMSP)

// ---------------------------------------------------------------------------
// Device-global scratch (allocation-free per harness rules)
// ---------------------------------------------------------------------------
__device__ __nv_bfloat16 g_x_hi[(size_t)B_ * T_ * I_];
__device__ __nv_bfloat16 g_x_lo[(size_t)B_ * T_ * I_];
__device__ __nv_bfloat16 g_h_hi[2][B_ * H_];
__device__ __nv_bfloat16 g_h_lo[2][B_ * H_];
__device__ __nv_bfloat16 g_Whh_hi[H_ * H_];
__device__ __nv_bfloat16 g_Whh_lo[H_ * H_];
__device__ __nv_bfloat16 g_Wih_hi[H_ * I_];
__device__ __nv_bfloat16 g_Wih_lo[H_ * I_];
__device__ float g_h32[B_ * H_];
__device__ unsigned g_bar_count;   // zero-init; restored to 0 by protocol
__device__ unsigned g_bar_phase;   // monotonic

// ---------------------------------------------------------------------------
// SMEM layout (dynamic): W slices persistent, 4-stage A pipeline
// ---------------------------------------------------------------------------
#define SM_WHH_HI 0            // 32 rows x 2048B
#define SM_WHH_LO 65536
#define SM_WIH_HI 131072       // 32 rows x 512B
#define SM_WIH_LO 147456
#define SM_ASTAGE 163840       // 4 stages x 16384 (hi 8KB + lo 8KB each)
#define SM_BIAS   229376       // 32 floats
#define SM_TOTAL  229632

// ---------------------------------------------------------------------------
// PTX helpers (portable ISA for plain sm_103 target — NO tcgen05)
// ---------------------------------------------------------------------------
__device__ __forceinline__ uint32_t smem_u32(const void* p) {
    uint32_t a;
    asm("{ .reg .u64 t; cvta.to.shared.u64 t, %1; cvt.u32.u64 %0, t; }" : "=r"(a) : "l"(p));
    return a;
}

__device__ __forceinline__ void cp16(uint32_t saddr, const void* gptr) {
    asm volatile("cp.async.cg.shared.global [%0], [%1], 16;"
                 :: "r"(saddr), "l"(__cvta_generic_to_global(gptr)));
}

__device__ __forceinline__ void ldsm_x4(uint32_t* r, uint32_t addr) {
    asm volatile("ldmatrix.sync.aligned.m8n8.x4.shared.b16 {%0,%1,%2,%3}, [%4];"
                 : "=r"(r[0]), "=r"(r[1]), "=r"(r[2]), "=r"(r[3]) : "r"(addr));
}

__device__ __forceinline__ void ldsm_x2(uint32_t* r, uint32_t addr) {
    asm volatile("ldmatrix.sync.aligned.m8n8.x2.shared.b16 {%0,%1}, [%2];"
                 : "=r"(r[0]), "=r"(r[1]) : "r"(addr));
}

__device__ __forceinline__ void mma16816(float* c, const uint32_t* a, uint32_t b0, uint32_t b1) {
    asm volatile(
        "mma.sync.aligned.m16n8k16.row.col.f32.bf16.bf16.f32 "
        "{%0,%1,%2,%3}, {%4,%5,%6,%7}, {%8,%9}, {%0,%1,%2,%3};"
        : "+f"(c[0]), "+f"(c[1]), "+f"(c[2]), "+f"(c[3])
        : "r"(a[0]), "r"(a[1]), "r"(a[2]), "r"(a[3]), "r"(b0), "r"(b1));
}

// Sense-reversing grid barrier (all NB CTAs co-resident by construction)
__device__ __forceinline__ void grid_barrier(unsigned* phase) {
    __syncthreads();
    if (threadIdx.x == 0) {
        unsigned target = *phase + 1;
        __threadfence();
        if (atomicAdd(&g_bar_count, 1) == NB - 1) {
            g_bar_count = 0;
            __threadfence();
            atomicExch(&g_bar_phase, target);
        } else {
            while (((volatile unsigned*)&g_bar_phase)[0] != target) {}
            __threadfence();
        }
        *phase = target;
    }
    __syncthreads();
}

// ---------------------------------------------------------------------------
// Split prep kernel
// ---------------------------------------------------------------------------
__global__ void split_pair(const float* __restrict__ src,
                           __nv_bfloat16* __restrict__ hi,
                           __nv_bfloat16* __restrict__ lo, int n)
{
    int i = blockIdx.x * blockDim.x + threadIdx.x;
    if (i < n) {
        float v = src[i];
        __nv_bfloat16 h = __float2bfloat16(v);
        hi[i] = h;
        lo[i] = __float2bfloat16(v - __bfloat162float(h));
    }
}

// ---------------------------------------------------------------------------
// A-stage chunk loaders (cp.async.cg -> L2-coherent across steps)
// Stage: hi 32 rows x 256B (swizzled), lo at +8192. 256 threads -> 2 units each.
// ---------------------------------------------------------------------------
__device__ __forceinline__ void load_chunk_h(uint32_t sstage,
    const char* __restrict__ hhi, const char* __restrict__ hlo, int m0, int c, int tid)
{
    #pragma unroll
    for (int i = 0; i < 2; i++) {
        int u = tid + i * NTHR;
        int row = u >> 4, uk = u & 15;
        int so = row * 256 + ((uk * 16) ^ ((row & 7) * 16));
        size_t go = (size_t)(m0 + row) * 2048 + (size_t)c * 256 + uk * 16;
        cp16(sstage + so, hhi + go);
        cp16(sstage + 8192 + so, hlo + go);
    }
}

__device__ __forceinline__ void load_chunk_x(uint32_t sstage, int m0, int cx, int t, int tid)
{
    #pragma unroll
    for (int i = 0; i < 2; i++) {
        int u = tid + i * NTHR;
        int row = u >> 4, uk = u & 15;
        int so = row * 256 + ((uk * 16) ^ ((row & 7) * 16));
        size_t go = ((size_t)(m0 + row) * T_ + t) * 512 + (size_t)cx * 256 + uk * 16;
        cp16(sstage + so, (const char*)g_x_hi + go);
        cp16(sstage + 8192 + so, (const char*)g_x_lo + go);
    }
}

// ---------------------------------------------------------------------------
// Persistent recurrence kernel: 512 steps, one launch.
// CTA (ctaM, ctaN): M-tile 32 batches, N-tile 32 hidden cols, K = 1024(h)+256(x).
// 8 warps, warp tile M16xN8 (wm = wid>>2, wn = wid&3).
// 4-stage cp.async pipeline, prefetch distance 2 (race-free stage reuse).
// 4 accumulator parities (kk&3) for 8 independent MMA chains per SMSP.
// ---------------------------------------------------------------------------
__global__ __launch_bounds__(NTHR, 1) void rnn_persistent(
    const float* __restrict__ b_ih, const float* __restrict__ b_hh)
{
    extern __shared__ char sm[];
    const uint32_t smb = smem_u32(sm);
    const int tid = threadIdx.x;
    const int lid = tid & 31;
    const int wid = tid >> 5;
    const int wm = wid >> 2, wn = wid & 3;
    const int ctaM = blockIdx.x >> 5;
    const int ctaN = blockIdx.x & 31;
    const int m0 = ctaM * 32;
    const int n0 = ctaN * 32;

    // ---- Load persistent W slices into swizzled smem ----
    {
        const char* whh_hi = (const char*)g_Whh_hi;
        const char* whh_lo = (const char*)g_Whh_lo;
        for (int u = tid; u < 4096; u += NTHR) {
            int row = u >> 7, uk = u & 127;
            int so = row * 2048 + ((uk * 16) ^ ((row & 7) * 16));
            size_t go = (size_t)(n0 + row) * 2048 + (size_t)uk * 16;
            *(uint4*)(sm + SM_WHH_HI + so) = *(const uint4*)(whh_hi + go);
            *(uint4*)(sm + SM_WHH_LO + so) = *(const uint4*)(whh_lo + go);
        }
        // W_ih slice: 32 rows x 512 B = 1024 16-byte units
        const char* wih_hi = (const char*)g_Wih_hi;
        const char* wih_lo = (const char*)g_Wih_lo;
        for (int u = tid; u < 1024; u += NTHR) {
            int row = u >> 5, uk = u & 31;
            int so = row * 512 + ((uk * 16) ^ ((row & 7) * 16));
            size_t go = (size_t)(n0 + row) * 512 + (size_t)uk * 16;
            *(uint4*)(sm + SM_WIH_HI + so) = *(const uint4*)(wih_hi + go);
            *(uint4*)(sm + SM_WIH_LO + so) = *(const uint4*)(wih_lo + go);
        }
        if (tid < 32)
            ((float*)(sm + SM_BIAS))[tid] = b_ih[n0 + tid] + b_hh[n0 + tid];
    }

    unsigned phase = 0;
    if (tid == 0) phase = ((volatile unsigned*)&g_bar_phase)[0];
    __syncthreads();

    // Per-lane fragment address constants.
    // A x4: lanes 0-7 (m0-7,klo), 8-15 (m8-15,klo), 16-23 (m0-7,khi), 24-31 (m8-15,khi)
    const int arow = (lid & 7) + ((lid >> 3) & 1) * 8;
    const int aka2 = ((lid >> 4) & 1) * 16;
    const int axor = (arow & 7) * 16;
    const uint32_t a_lane = smb + SM_ASTAGE + (uint32_t)(wm * 16 + arow) * 256;

    // B x2 (N8): lanes 0-7 (n0-7,klo), 8-15 (n0-7,khi); W tile is [n][k] row-major,
    // NON-trans ldmatrix gives consecutive-k pairs at fixed n (mma B layout).
    const int brow = wn * 8 + (lid & 7);
    const int bka2 = ((lid >> 3) & 1) * 16;
    const int bxor = (brow & 7) * 16;
    const uint32_t bhh_lane = smb + SM_WHH_HI + (uint32_t)brow * 2048;
    const uint32_t bih_lane = smb + SM_WIH_HI + (uint32_t)brow * 512;

    const int g  = lid >> 2;
    const int tg = lid & 3;

    for (int t = 0; t < T_; t++) {
        const char* hhi = (const char*)g_h_hi[t & 1];
        const char* hlo = (const char*)g_h_lo[t & 1];

        float acc[4][4];
        #pragma unroll
        for (int p = 0; p < 4; p++)
            #pragma unroll
            for (int j = 0; j < 4; j++) acc[p][j] = 0.f;

        // Prologue: chunks 0,1 into stages 0,1
        load_chunk_h(smb + SM_ASTAGE, hhi, hlo, m0, 0, tid);
        asm volatile("cp.async.commit_group;");
        load_chunk_h(smb + SM_ASTAGE + 16384, hhi, hlo, m0, 1, tid);
        asm volatile("cp.async.commit_group;");

        // K pipeline: chunks 0..7 = h (K=1024), chunks 8..9 = x_t (K=256)
        for (int c = 0; c < 10; c++) {
            if (c + 2 < 10) {
                uint32_t st = smb + SM_ASTAGE + (uint32_t)((c + 2) & 3) * 16384;
                if (c + 2 < 8) load_chunk_h(st, hhi, hlo, m0, c + 2, tid);
                else           load_chunk_x(st, m0, c + 2 - 8, t, tid);
                asm volatile("cp.async.commit_group;");
            }
            if (c < 8)       asm volatile("cp.async.wait_group 2;");
            else if (c == 8) asm volatile("cp.async.wait_group 1;");
            else             asm volatile("cp.async.wait_group 0;");
            __syncthreads();

            const uint32_t a_base = a_lane + (uint32_t)(c & 3) * 16384;
            uint32_t b_base, b_dlo;
            int kb0;
            if (c < 8) { b_base = bhh_lane; b_dlo = 65536; kb0 = c * 256; }
            else       { b_base = bih_lane; b_dlo = 16384; kb0 = (c - 8) * 256; }

            #pragma unroll
            for (int kk = 0; kk < 8; kk++) {
                uint32_t ahi[4], alo[4], bh[2], bl[2];
                uint32_t ao = (uint32_t)((kk * 32 + aka2) ^ axor);
                ldsm_x4(ahi, a_base + ao);
                ldsm_x4(alo, a_base + 8192 + ao);
                uint32_t bo = (uint32_t)((kb0 + kk * 32 + bka2) ^ bxor);
                ldsm_x2(bh, b_base + bo);
                ldsm_x2(bl, b_base + b_dlo + bo);

                float* C = acc[kk & 3];
                mma16816(C, ahi, bh[0], bh[1]);   // Ahi*Bhi
                mma16816(C, ahi, bl[0], bl[1]);   // Ahi*Blo
                mma16816(C, alo, bh[0], bh[1]);   // Alo*Bhi
            }
            // No end-of-loop sync needed: 4 stages + distance-2 prefetch means the
            // stage reused at iter c was last read at iter c-2, separated by the
            // iter c-1 barrier from any iter-c cp.async issue.
        }

        // Epilogue: +bias, tanh, split-bf16 store of h_{t+1}
        {
            __nv_bfloat16* __restrict__ ohi = g_h_hi[(t + 1) & 1];
            __nv_bfloat16* __restrict__ olo = g_h_lo[(t + 1) & 1];
            const float* bias = (const float*)(sm + SM_BIAS);
            const bool last = (t == T_ - 1);

            float vsum[4];
            #pragma unroll
            for (int j = 0; j < 4; j++)
                vsum[j] = acc[0][j] + acc[1][j] + acc[2][j] + acc[3][j];

            int nloc = wn * 8 + tg * 2;
            int ng = n0 + nloc;
            float b0v = bias[nloc], b1v = bias[nloc + 1];
            #pragma unroll
            for (int rp = 0; rp < 2; rp++) {
                int mg = m0 + wm * 16 + g + rp * 8;
                float v0 = tanhf(vsum[rp * 2 + 0] + b0v);
                float v1 = tanhf(vsum[rp * 2 + 1] + b1v);
                __nv_bfloat16 h0 = __float2bfloat16(v0);
                __nv_bfloat16 h1 = __float2bfloat16(v1);
                __nv_bfloat16 l0 = __float2bfloat16(v0 - __bfloat162float(h0));
                __nv_bfloat16 l1 = __float2bfloat16(v1 - __bfloat162float(h1));
                size_t idx = (size_t)mg * H_ + ng;
                *(uint32_t*)(ohi + idx) =
                    ((uint32_t)*(uint16_t*)&h1 << 16) | *(uint16_t*)&h0;
                *(uint32_t*)(olo + idx) =
                    ((uint32_t)*(uint16_t*)&l1 << 16) | *(uint16_t*)&l0;
                if (last) {
                    float2 f2v; f2v.x = v0; f2v.y = v1;
                    *(float2*)(g_h32 + idx) = f2v;
                }
            }
        }

        grid_barrier(&phase);
    }
}

// ---------------------------------------------------------------------------
// fc epilogue on final hidden state
// ---------------------------------------------------------------------------
__global__ __launch_bounds__(256) void fc_kernel(
    const float* __restrict__ W_fc, const float* __restrict__ b_fc,
    float* __restrict__ out)
{
    __shared__ float hsv[H_];
    const int b = blockIdx.x;
    const int tid = threadIdx.x;
    for (int k = tid; k < H_; k += 256) hsv[k] = g_h32[(size_t)b * H_ + k];
    __syncthreads();

    const int o = tid;
    const float* __restrict__ wrow = W_fc + (size_t)o * H_;
    float acc = 0.f;
    #pragma unroll 8
    for (int k = 0; k < H_; k++) acc = fmaf(hsv[k], wrow[k], acc);
    out[(size_t)b * O_ + o] = acc + b_fc[o];
}

__global__ void copy_hidden(float* __restrict__ dst)
{
    int idx = blockIdx.x * blockDim.x + threadIdx.x;
    if (idx < B_ * H_) dst[idx] = g_h32[idx];
}

// ---------------------------------------------------------------------------
extern "C" void kernel_launch(void* const* d_in, const int* in_sizes, int n_in,
                              void* d_out, int out_size)
{
    const float* x      = (const float*)d_in[0];
    const float* hidden = (const float*)d_in[1];
    const float* W_ih   = (const float*)d_in[2];
    const float* W_hh   = (const float*)d_in[3];
    const float* b_ih   = (const float*)d_in[4];
    const float* b_hh   = (const float*)d_in[5];
    const float* W_fc   = (const float*)d_in[6];
    const float* b_fc   = (const float*)d_in[7];
    float* out = (float*)d_out;

    cudaFuncSetAttribute(rnn_persistent, cudaFuncAttributeMaxDynamicSharedMemorySize,
                         SM_TOTAL);

    // Resolve device-global scratch addresses (host-side, not a stream op)
    static __nv_bfloat16 *p_xhi = nullptr, *p_xlo = nullptr, *p_whhhi = nullptr,
                         *p_whhlo = nullptr, *p_wihhi = nullptr, *p_wihlo = nullptr,
                         *p_hhi = nullptr, *p_hlo = nullptr;
    if (!p_xhi) {
        cudaGetSymbolAddress((void**)&p_xhi,   g_x_hi);
        cudaGetSymbolAddress((void**)&p_xlo,   g_x_lo);
        cudaGetSymbolAddress((void**)&p_whhhi, g_Whh_hi);
        cudaGetSymbolAddress((void**)&p_whhlo, g_Whh_lo);
        cudaGetSymbolAddress((void**)&p_wihhi, g_Wih_hi);
        cudaGetSymbolAddress((void**)&p_wihlo, g_Wih_lo);
        cudaGetSymbolAddress((void**)&p_hhi,   g_h_hi);
        cudaGetSymbolAddress((void**)&p_hlo,   g_h_lo);
    }

    // 1) split inputs to bf16 hi/lo
    split_pair<<<(B_ * T_ * I_ + 255) / 256, 256>>>(x, p_xhi, p_xlo, B_ * T_ * I_);
    split_pair<<<(H_ * H_ + 255) / 256, 256>>>(W_hh, p_whhhi, p_whhlo, H_ * H_);
    split_pair<<<(H_ * I_ + 255) / 256, 256>>>(W_ih, p_wihhi, p_wihlo, H_ * I_);
    split_pair<<<(B_ * H_ + 255) / 256, 256>>>(hidden, p_hhi, p_hlo, B_ * H_);

    // 2) full recurrence in ONE persistent launch
    rnn_persistent<<<NB, NTHR, SM_TOTAL>>>(b_ih, b_hh);

    // 3) fc epilogue + hidden output
    fc_kernel<<<B_, 256>>>(W_fc, b_fc, out);
    if (out_size >= B_ * O_ + B_ * H_)
        copy_hidden<<<(B_ * H_ + 255) / 256, 256>>>(out + B_ * O_);
}

// round 11
// speedup vs baseline: 1.2328x; 1.2328x over previous
#include <cuda_runtime.h>
#include <cuda_bf16.h>
#include <math.h>
#include <stdint.h>

// Problem constants
#define B_ 128
#define T_ 512
#define I_ 256
#define H_ 1024
#define O_ 256

#define NB   128      // persistent grid: 4 M-tiles x 32 N-tiles
#define NTHR 256      // 8 warps: warps 0-3 = stream 0 (even chunks), 4-7 = stream 1 (odd)

// ---------------------------------------------------------------------------
// Device-global scratch (allocation-free per harness rules)
// ---------------------------------------------------------------------------
__device__ __nv_bfloat16 g_x_hi[(size_t)B_ * T_ * I_];
__device__ __nv_bfloat16 g_x_lo[(size_t)B_ * T_ * I_];
__device__ __nv_bfloat16 g_h_hi[2][B_ * H_];
__device__ __nv_bfloat16 g_h_lo[2][B_ * H_];
__device__ float g_h32[B_ * H_];
__device__ unsigned g_bar_count;   // zero-init; returns to 0 each barrier
__device__ unsigned g_bar_phase;   // monotonic

// ---------------------------------------------------------------------------
// SMEM layout (dynamic)
// ---------------------------------------------------------------------------
#define SM_WHH_HI 0            // 32 rows x 2048B, swizzled (col XOR row)
#define SM_WHH_LO 65536
#define SM_WIH_HI 131072       // 32 rows x 512B, swizzled (col XOR row)
#define SM_WIH_LO 147456
#define SM_ASTAGE 163840       // per stream: 2 stages x 16KB; stream1 at +32768
#define SM_RED    (SM_ASTAGE + 32768)   // reduction buffer reuses stream1 stage 0
#define SM_BIAS   229376       // 32 floats
#define SM_TOTAL  229632

// ---------------------------------------------------------------------------
// PTX helpers (portable ISA for plain sm_103 target — NO tcgen05)
// ---------------------------------------------------------------------------
__device__ __forceinline__ uint32_t smem_u32(const void* p) {
    uint32_t a;
    asm("{ .reg .u64 t; cvta.to.shared.u64 t, %1; cvt.u32.u64 %0, t; }" : "=r"(a) : "l"(p));
    return a;
}

__device__ __forceinline__ void cp16(uint32_t saddr, const void* gptr) {
    asm volatile("cp.async.cg.shared.global [%0], [%1], 16;"
                 :: "r"(saddr), "l"(__cvta_generic_to_global(gptr)));
}

__device__ __forceinline__ void ldsm_x4(uint32_t* r, uint32_t addr) {
    asm volatile("ldmatrix.sync.aligned.m8n8.x4.shared.b16 {%0,%1,%2,%3}, [%4];"
                 : "=r"(r[0]), "=r"(r[1]), "=r"(r[2]), "=r"(r[3]) : "r"(addr));
}

__device__ __forceinline__ void mma16816(float* c, const uint32_t* a, uint32_t b0, uint32_t b1) {
    asm volatile(
        "mma.sync.aligned.m16n8k16.row.col.f32.bf16.bf16.f32 "
        "{%0,%1,%2,%3}, {%4,%5,%6,%7}, {%8,%9}, {%0,%1,%2,%3};"
        : "+f"(c[0]), "+f"(c[1]), "+f"(c[2]), "+f"(c[3])
        : "r"(a[0]), "r"(a[1]), "r"(a[2]), "r"(a[3]), "r"(b0), "r"(b1));
}

__device__ __forceinline__ void stream_bar(int stream) {
    asm volatile("bar.sync %0, 128;" :: "r"(1 + stream) : "memory");
}

// Sense-reversing grid barrier (all NB CTAs co-resident by construction)
__device__ __forceinline__ void grid_barrier(unsigned* phase) {
    __syncthreads();
    if (threadIdx.x == 0) {
        unsigned target = *phase + 1;
        if (atomicAdd(&g_bar_count, 1) == NB - 1) {
            g_bar_count = 0;
            __threadfence();
            atomicExch(&g_bar_phase, target);
        } else {
            while (((volatile unsigned*)&g_bar_phase)[0] != target) {}
            __threadfence();
        }
        *phase = target;
    }
    __syncthreads();
}

// ---------------------------------------------------------------------------
// Split prep kernel (x and initial hidden only; W splits happen in prologue)
// ---------------------------------------------------------------------------
__global__ void split_pair(const float* __restrict__ src,
                           __nv_bfloat16* __restrict__ hi,
                           __nv_bfloat16* __restrict__ lo, int n)
{
    int i = blockIdx.x * blockDim.x + threadIdx.x;
    if (i < n) {
        float v = src[i];
        __nv_bfloat16 h = __float2bfloat16(v);
        hi[i] = h;
        lo[i] = __float2bfloat16(v - __bfloat162float(h));
    }
}

// ---------------------------------------------------------------------------
// Stream-local chunk loader: 128 threads load 16KB (hi 8KB + lo 8KB).
// Swizzle convention everywhere: column offset XOR ((row&7)*16).
// Chunk c: c<8 -> h slice (K cols c*128..), c>=8 -> x_t slice.
// ---------------------------------------------------------------------------
__device__ __forceinline__ void load_chunk(uint32_t sstage, int c,
    const char* __restrict__ hhi, const char* __restrict__ hlo,
    int m0, int t, int stid)
{
    if (c < 8) {
        #pragma unroll
        for (int i = 0; i < 4; i++) {
            int u = stid + i * 128;
            int row = u >> 4, uk = u & 15;
            int so = row * 256 + ((uk * 16) ^ ((row & 7) * 16));
            size_t go = (size_t)(m0 + row) * 2048 + (size_t)c * 256 + uk * 16;
            cp16(sstage + so, hhi + go);
            cp16(sstage + 8192 + so, hlo + go);
        }
    } else {
        int cx = c - 8;
        #pragma unroll
        for (int i = 0; i < 4; i++) {
            int u = stid + i * 128;
            int row = u >> 4, uk = u & 15;
            int so = row * 256 + ((uk * 16) ^ ((row & 7) * 16));
            size_t go = ((size_t)(m0 + row) * T_ + t) * 512 + (size_t)cx * 256 + uk * 16;
            cp16(sstage + so, (const char*)g_x_hi + go);
            cp16(sstage + 8192 + so, (const char*)g_x_lo + go);
        }
    }
}

// ---------------------------------------------------------------------------
// Persistent recurrence kernel: 512 steps, one launch.
// CTA (ctaM, ctaN): M-tile 32 batches, N-tile 32 cols, K = 1024(h)+256(x).
// Dual K-parity streams of 4 warps each (M16xN16 warp tiles), so every SMSP
// runs 2 independent warps: LDS of one overlaps HMMA of the other.
// ---------------------------------------------------------------------------
__global__ __launch_bounds__(NTHR, 1) void rnn_persistent(
    const float* __restrict__ b_ih, const float* __restrict__ b_hh,
    const float* __restrict__ Whh, const float* __restrict__ Wih)
{
    extern __shared__ char sm[];
    const uint32_t smb = smem_u32(sm);
    const int tid = threadIdx.x;
    const int lid = tid & 31;
    const int wid = tid >> 5;
    const int stream = wid >> 2;          // 0: even chunks, 1: odd chunks
    const int stid = tid & 127;           // stream-local thread id
    const int swid = wid & 3;
    const int wm = swid >> 1, wn = swid & 1;
    const int ctaM = blockIdx.x >> 5;
    const int ctaN = blockIdx.x & 31;
    const int m0 = ctaM * 32;
    const int n0 = ctaN * 32;

    // ---- Prologue: split W slices fp32 -> bf16 hi/lo directly into smem.
    // Store swizzle MUST match ldmatrix read path: (col16B) ^ ((row&7)*16).
    // (R9 bug: used offset-bit swizzle SWZ() here -> permuted W fragments.)
    {
        // W_hh slice: 32 rows x 1024 floats = 8192 float4 units
        for (int u = tid; u < 8192; u += NTHR) {
            int row = u >> 8, k4 = u & 255;   // k4: 8-byte unit within row
            float4 v = *(const float4*)(Whh + (size_t)(n0 + row) * H_ + k4 * 4);
            __nv_bfloat162 h01 = __floats2bfloat162_rn(v.x, v.y);
            __nv_bfloat162 h23 = __floats2bfloat162_rn(v.z, v.w);
            __nv_bfloat162 l01 = __floats2bfloat162_rn(
                v.x - __bfloat162float(h01.x), v.y - __bfloat162float(h01.y));
            __nv_bfloat162 l23 = __floats2bfloat162_rn(
                v.z - __bfloat162float(h23.x), v.w - __bfloat162float(h23.y));
            int so = row * 2048 + ((k4 * 8) ^ ((row & 7) * 16));
            uint2 hp; hp.x = *(uint32_t*)&h01; hp.y = *(uint32_t*)&h23;
            uint2 lp; lp.x = *(uint32_t*)&l01; lp.y = *(uint32_t*)&l23;
            *(uint2*)(sm + SM_WHH_HI + so) = hp;
            *(uint2*)(sm + SM_WHH_LO + so) = lp;
        }
        // W_ih slice: 32 rows x 256 floats = 2048 float4 units
        for (int u = tid; u < 2048; u += NTHR) {
            int row = u >> 6, k4 = u & 63;
            float4 v = *(const float4*)(Wih + (size_t)(n0 + row) * I_ + k4 * 4);
            __nv_bfloat162 h01 = __floats2bfloat162_rn(v.x, v.y);
            __nv_bfloat162 h23 = __floats2bfloat162_rn(v.z, v.w);
            __nv_bfloat162 l01 = __floats2bfloat162_rn(
                v.x - __bfloat162float(h01.x), v.y - __bfloat162float(h01.y));
            __nv_bfloat162 l23 = __floats2bfloat162_rn(
                v.z - __bfloat162float(h23.x), v.w - __bfloat162float(h23.y));
            int so = row * 512 + ((k4 * 8) ^ ((row & 7) * 16));
            uint2 hp; hp.x = *(uint32_t*)&h01; hp.y = *(uint32_t*)&h23;
            uint2 lp; lp.x = *(uint32_t*)&l01; lp.y = *(uint32_t*)&l23;
            *(uint2*)(sm + SM_WIH_HI + so) = hp;
            *(uint2*)(sm + SM_WIH_LO + so) = lp;
        }
        if (tid < 32)
            ((float*)(sm + SM_BIAS))[tid] = b_ih[n0 + tid] + b_hh[n0 + tid];
    }

    unsigned phase = 0;
    if (tid == 0) phase = ((volatile unsigned*)&g_bar_phase)[0];
    __syncthreads();

    // Per-lane fragment address constants (proven in R7)
    const int arow = (lid & 7) + ((lid >> 3) & 1) * 8;
    const int aka2 = ((lid >> 4) & 1) * 16;
    const int axor = (arow & 7) * 16;
    const uint32_t stage_base = smb + SM_ASTAGE + (uint32_t)stream * 32768;
    const uint32_t a_lane = stage_base + (uint32_t)(wm * 16 + arow) * 256;

    const int brow = wn * 16 + (lid & 7) + ((lid >> 4) & 1) * 8;
    const int bka2 = ((lid >> 3) & 1) * 16;
    const int bxor = (brow & 7) * 16;
    const uint32_t bhh_lane = smb + SM_WHH_HI + (uint32_t)brow * 2048;
    const uint32_t bih_lane = smb + SM_WIH_HI + (uint32_t)brow * 512;

    const int g  = lid >> 2;
    const int tg = lid & 3;

    for (int t = 0; t < T_; t++) {
        const char* hhi = (const char*)g_h_hi[t & 1];
        const char* hlo = (const char*)g_h_lo[t & 1];

        float acc[2][2][4];
        #pragma unroll
        for (int p = 0; p < 2; p++)
            #pragma unroll
            for (int n = 0; n < 2; n++)
                #pragma unroll
                for (int j = 0; j < 4; j++) acc[p][n][j] = 0.f;

        // Stream s handles chunks {s, s+2, ..., s+8} (5 chunks), 2 private stages.
        load_chunk(stage_base, stream, hhi, hlo, m0, t, stid);
        asm volatile("cp.async.commit_group;");

        #pragma unroll
        for (int i = 0; i < 5; i++) {
            asm volatile("cp.async.wait_group 0;");   // chunk i data in
            stream_bar(stream);   // data visible to all stream warps; all done mma(i-1)
            const int c = 2 * i + stream;
            if (i < 4) {          // prefetch next chunk into the now-free stage
                load_chunk(stage_base + (uint32_t)((i + 1) & 1) * 16384,
                           c + 2, hhi, hlo, m0, t, stid);
                asm volatile("cp.async.commit_group;");
            }

            const uint32_t a_base = a_lane + (uint32_t)(i & 1) * 16384;
            uint32_t b_base, b_dlo;
            int kb0;
            if (c < 8) { b_base = bhh_lane; b_dlo = 65536; kb0 = c * 256; }
            else       { b_base = bih_lane; b_dlo = 16384; kb0 = (c - 8) * 256; }

            #pragma unroll
            for (int kk = 0; kk < 8; kk++) {
                uint32_t ahi[4], alo[4], bh[4], bl[4];
                uint32_t ao = (uint32_t)((kk * 32 + aka2) ^ axor);
                ldsm_x4(ahi, a_base + ao);
                ldsm_x4(alo, a_base + 8192 + ao);
                uint32_t bo = (uint32_t)((kb0 + kk * 32 + bka2) ^ bxor);
                ldsm_x4(bh, b_base + bo);          // NON-trans: [n][k] row-major
                ldsm_x4(bl, b_base + b_dlo + bo);

                float* C0 = acc[kk & 1][0];
                float* C1 = acc[kk & 1][1];
                mma16816(C0, ahi, bh[0], bh[1]);   // Ahi*Bhi
                mma16816(C1, ahi, bh[2], bh[3]);
                mma16816(C0, ahi, bl[0], bl[1]);   // Ahi*Blo
                mma16816(C1, ahi, bl[2], bl[3]);
                mma16816(C0, alo, bh[0], bh[1]);   // Alo*Bhi
                mma16816(C1, alo, bh[2], bh[3]);
            }
        }
        stream_bar(stream);   // all stream warps done with stages before red reuse

        // ---- Epilogue: merge streams, +bias, tanh, split-bf16 store ----
        {
            float vs[2][4];
            #pragma unroll
            for (int nt = 0; nt < 2; nt++)
                #pragma unroll
                for (int j = 0; j < 4; j++)
                    vs[nt][j] = acc[0][nt][j] + acc[1][nt][j];

            float* red = (float*)(sm + SM_RED);   // stream1 stage area (now idle)
            if (stream == 1) {
                #pragma unroll
                for (int nt = 0; nt < 2; nt++) {
                    int nloc = wn * 16 + nt * 8 + tg * 2;
                    #pragma unroll
                    for (int rp = 0; rp < 2; rp++) {
                        int mloc = wm * 16 + g + rp * 8;
                        red[mloc * 32 + nloc]     = vs[nt][rp * 2 + 0];
                        red[mloc * 32 + nloc + 1] = vs[nt][rp * 2 + 1];
                    }
                }
            }
            __syncthreads();
            if (stream == 0) {
                __nv_bfloat16* __restrict__ ohi = g_h_hi[(t + 1) & 1];
                __nv_bfloat16* __restrict__ olo = g_h_lo[(t + 1) & 1];
                const float* bias = (const float*)(sm + SM_BIAS);
                const bool last = (t == T_ - 1);
                #pragma unroll
                for (int nt = 0; nt < 2; nt++) {
                    int nloc = wn * 16 + nt * 8 + tg * 2;
                    int ng = n0 + nloc;
                    float b0v = bias[nloc], b1v = bias[nloc + 1];
                    #pragma unroll
                    for (int rp = 0; rp < 2; rp++) {
                        int mloc = wm * 16 + g + rp * 8;
                        int mg = m0 + mloc;
                        float v0 = tanhf(vs[nt][rp * 2 + 0] + red[mloc * 32 + nloc] + b0v);
                        float v1 = tanhf(vs[nt][rp * 2 + 1] + red[mloc * 32 + nloc + 1] + b1v);
                        __nv_bfloat16 h0 = __float2bfloat16(v0);
                        __nv_bfloat16 h1 = __float2bfloat16(v1);
                        __nv_bfloat16 l0 = __float2bfloat16(v0 - __bfloat162float(h0));
                        __nv_bfloat16 l1 = __float2bfloat16(v1 - __bfloat162float(h1));
                        size_t idx = (size_t)mg * H_ + ng;
                        *(uint32_t*)(ohi + idx) =
                            ((uint32_t)*(uint16_t*)&h1 << 16) | *(uint16_t*)&h0;
                        *(uint32_t*)(olo + idx) =
                            ((uint32_t)*(uint16_t*)&l1 << 16) | *(uint16_t*)&l0;
                        if (last) {
                            float2 f2v; f2v.x = v0; f2v.y = v1;
                            *(float2*)(g_h32 + idx) = f2v;
                        }
                    }
                }
            }
        }

        __threadfence();   // make h stores visible GPU-wide before barrier release
        grid_barrier(&phase);
    }
}

// ---------------------------------------------------------------------------
// fc epilogue on final hidden state
// ---------------------------------------------------------------------------
__global__ __launch_bounds__(256) void fc_kernel(
    const float* __restrict__ W_fc, const float* __restrict__ b_fc,
    float* __restrict__ out)
{
    __shared__ float hsv[H_];
    const int b = blockIdx.x;
    const int tid = threadIdx.x;
    for (int k = tid; k < H_; k += 256) hsv[k] = g_h32[(size_t)b * H_ + k];
    __syncthreads();

    const int o = tid;
    const float* __restrict__ wrow = W_fc + (size_t)o * H_;
    float acc = 0.f;
    #pragma unroll 8
    for (int k = 0; k < H_; k++) acc = fmaf(hsv[k], wrow[k], acc);
    out[(size_t)b * O_ + o] = acc + b_fc[o];
}

__global__ void copy_hidden(float* __restrict__ dst)
{
    int idx = blockIdx.x * blockDim.x + threadIdx.x;
    if (idx < B_ * H_) dst[idx] = g_h32[idx];
}

// ---------------------------------------------------------------------------
extern "C" void kernel_launch(void* const* d_in, const int* in_sizes, int n_in,
                              void* d_out, int out_size)
{
    const float* x      = (const float*)d_in[0];
    const float* hidden = (const float*)d_in[1];
    const float* W_ih   = (const float*)d_in[2];
    const float* W_hh   = (const float*)d_in[3];
    const float* b_ih   = (const float*)d_in[4];
    const float* b_hh   = (const float*)d_in[5];
    const float* W_fc   = (const float*)d_in[6];
    const float* b_fc   = (const float*)d_in[7];
    float* out = (float*)d_out;

    cudaFuncSetAttribute(rnn_persistent, cudaFuncAttributeMaxDynamicSharedMemorySize,
                         SM_TOTAL);

    // Resolve device-global scratch addresses (host-side, not a stream op)
    static __nv_bfloat16 *p_xhi = nullptr, *p_xlo = nullptr,
                         *p_hhi = nullptr, *p_hlo = nullptr;
    if (!p_xhi) {
        cudaGetSymbolAddress((void**)&p_xhi, g_x_hi);
        cudaGetSymbolAddress((void**)&p_xlo, g_x_lo);
        cudaGetSymbolAddress((void**)&p_hhi, g_h_hi);
        cudaGetSymbolAddress((void**)&p_hlo, g_h_lo);
    }

    // 1) split x and initial hidden to bf16 hi/lo (W splits live in the prologue)
    split_pair<<<(B_ * T_ * I_ + 255) / 256, 256>>>(x, p_xhi, p_xlo, B_ * T_ * I_);
    split_pair<<<(B_ * H_ + 255) / 256, 256>>>(hidden, p_hhi, p_hlo, B_ * H_);

    // 2) full recurrence in ONE persistent launch
    rnn_persistent<<<NB, NTHR, SM_TOTAL>>>(b_ih, b_hh, W_hh, W_ih);

    // 3) fc epilogue + hidden output
    fc_kernel<<<B_, 256>>>(W_fc, b_fc, out);
    if (out_size >= B_ * O_ + B_ * H_)
        copy_hidden<<<(B_ * H_ + 255) / 256, 256>>>(out + B_ * O_);
}

// round 12
// speedup vs baseline: 1.3061x; 1.0594x over previous
#include <cuda_runtime.h>
#include <cuda_bf16.h>
#include <math.h>
#include <stdint.h>

// Problem constants
#define B_ 128
#define T_ 512
#define I_ 256
#define H_ 1024
#define O_ 256

#define NB   128      // persistent grid: 4 M-tiles x 32 N-tiles
#define NTHR 256      // 8 warps: warps 0-3 = stream 0 (even chunks), 4-7 = stream 1 (odd)

// ---------------------------------------------------------------------------
// Device-global scratch (allocation-free per harness rules)
// ---------------------------------------------------------------------------
__device__ __nv_bfloat16 g_x_hi[(size_t)B_ * T_ * I_];
__device__ __nv_bfloat16 g_x_lo[(size_t)B_ * T_ * I_];
__device__ __nv_bfloat16 g_h_hi[2][B_ * H_];
__device__ __nv_bfloat16 g_h_lo[2][B_ * H_];
__device__ float g_h32[B_ * H_];
// Group-local barriers: batch-group g uses slot g*32 (128B padding, no false sharing)
__device__ unsigned g_bar_count4[128];   // zero-init; returns to 0 each barrier
__device__ unsigned g_bar_phase4[128];   // monotonic

// ---------------------------------------------------------------------------
// SMEM layout (dynamic)
// ---------------------------------------------------------------------------
#define SM_WHH_HI 0            // 32 rows x 2048B, swizzled (col XOR row)
#define SM_WHH_LO 65536
#define SM_WIH_HI 131072       // 32 rows x 512B, swizzled (col XOR row)
#define SM_WIH_LO 147456
#define SM_ASTAGE 163840       // per stream: 2 stages x 16KB; stream1 at +32768
#define SM_RED    (SM_ASTAGE + 32768)   // reduction buffer reuses stream1 stage 0
#define SM_BIAS   229376       // 32 floats
#define SM_TOTAL  229632

// ---------------------------------------------------------------------------
// PTX helpers (portable ISA for plain sm_103 target — NO tcgen05)
// ---------------------------------------------------------------------------
__device__ __forceinline__ uint32_t smem_u32(const void* p) {
    uint32_t a;
    asm("{ .reg .u64 t; cvta.to.shared.u64 t, %1; cvt.u32.u64 %0, t; }" : "=r"(a) : "l"(p));
    return a;
}

__device__ __forceinline__ void cp16(uint32_t saddr, const void* gptr) {
    asm volatile("cp.async.cg.shared.global [%0], [%1], 16;"
                 :: "r"(saddr), "l"(__cvta_generic_to_global(gptr)));
}

__device__ __forceinline__ void ldsm_x4(uint32_t* r, uint32_t addr) {
    asm volatile("ldmatrix.sync.aligned.m8n8.x4.shared.b16 {%0,%1,%2,%3}, [%4];"
                 : "=r"(r[0]), "=r"(r[1]), "=r"(r[2]), "=r"(r[3]) : "r"(addr));
}

__device__ __forceinline__ void mma16816(float* c, const uint32_t* a, uint32_t b0, uint32_t b1) {
    asm volatile(
        "mma.sync.aligned.m16n8k16.row.col.f32.bf16.bf16.f32 "
        "{%0,%1,%2,%3}, {%4,%5,%6,%7}, {%8,%9}, {%0,%1,%2,%3};"
        : "+f"(c[0]), "+f"(c[1]), "+f"(c[2]), "+f"(c[3])
        : "r"(a[0]), "r"(a[1]), "r"(a[2]), "r"(a[3]), "r"(b0), "r"(b1));
}

__device__ __forceinline__ void stream_bar(int stream) {
    asm volatile("bar.sync %0, 128;" :: "r"(1 + stream) : "memory");
}

// Group-local sense-reversing barrier: 32 CTAs sharing a batch group (ctaM).
// Valid because h rows of group g are produced AND consumed only by group g.
__device__ __forceinline__ void group_barrier(int grp, unsigned* phase) {
    __syncthreads();
    if (threadIdx.x == 0) {
        unsigned target = *phase + 1;
        unsigned* cnt = &g_bar_count4[grp * 32];
        unsigned* ph  = &g_bar_phase4[grp * 32];
        if (atomicAdd(cnt, 1) == 31) {
            *cnt = 0;
            __threadfence();
            atomicExch(ph, target);
        } else {
            while (((volatile unsigned*)ph)[0] != target) {}
            __threadfence();
        }
        *phase = target;
    }
    __syncthreads();
}

// ---------------------------------------------------------------------------
// Split prep kernel (x and initial hidden only; W splits happen in prologue)
// ---------------------------------------------------------------------------
__global__ void split_pair(const float* __restrict__ src,
                           __nv_bfloat16* __restrict__ hi,
                           __nv_bfloat16* __restrict__ lo, int n)
{
    int i = blockIdx.x * blockDim.x + threadIdx.x;
    if (i < n) {
        float v = src[i];
        __nv_bfloat16 h = __float2bfloat16(v);
        hi[i] = h;
        lo[i] = __float2bfloat16(v - __bfloat162float(h));
    }
}

// ---------------------------------------------------------------------------
// Stream-local chunk loader: 128 threads load 16KB (hi 8KB + lo 8KB).
// Swizzle convention everywhere: column offset XOR ((row&7)*16).
// Chunk c: c<8 -> h slice (K cols c*128..), c>=8 -> x_t slice.
// ---------------------------------------------------------------------------
__device__ __forceinline__ void load_chunk(uint32_t sstage, int c,
    const char* __restrict__ hhi, const char* __restrict__ hlo,
    int m0, int t, int stid)
{
    if (c < 8) {
        #pragma unroll
        for (int i = 0; i < 4; i++) {
            int u = stid + i * 128;
            int row = u >> 4, uk = u & 15;
            int so = row * 256 + ((uk * 16) ^ ((row & 7) * 16));
            size_t go = (size_t)(m0 + row) * 2048 + (size_t)c * 256 + uk * 16;
            cp16(sstage + so, hhi + go);
            cp16(sstage + 8192 + so, hlo + go);
        }
    } else {
        int cx = c - 8;
        #pragma unroll
        for (int i = 0; i < 4; i++) {
            int u = stid + i * 128;
            int row = u >> 4, uk = u & 15;
            int so = row * 256 + ((uk * 16) ^ ((row & 7) * 16));
            size_t go = ((size_t)(m0 + row) * T_ + t) * 512 + (size_t)cx * 256 + uk * 16;
            cp16(sstage + so, (const char*)g_x_hi + go);
            cp16(sstage + 8192 + so, (const char*)g_x_lo + go);
        }
    }
}

// ---------------------------------------------------------------------------
// Persistent recurrence kernel: 512 steps, one launch.
// CTA (ctaM, ctaN): M-tile 32 batches, N-tile 32 cols, K = 1024(h)+256(x).
// Dual K-parity streams of 4 warps each (M16xN16 warp tiles); group-local
// barriers (4 independent 32-CTA groups along the batch dimension).
// ---------------------------------------------------------------------------
__global__ __launch_bounds__(NTHR, 1) void rnn_persistent(
    const float* __restrict__ b_ih, const float* __restrict__ b_hh,
    const float* __restrict__ Whh, const float* __restrict__ Wih)
{
    extern __shared__ char sm[];
    const uint32_t smb = smem_u32(sm);
    const int tid = threadIdx.x;
    const int lid = tid & 31;
    const int wid = tid >> 5;
    const int stream = wid >> 2;          // 0: even chunks, 1: odd chunks
    const int stid = tid & 127;           // stream-local thread id
    const int swid = wid & 3;
    const int wm = swid >> 1, wn = swid & 1;
    const int ctaM = blockIdx.x >> 5;
    const int ctaN = blockIdx.x & 31;
    const int m0 = ctaM * 32;
    const int n0 = ctaN * 32;

    // ---- Prologue: split W slices fp32 -> bf16 hi/lo directly into smem.
    // Store swizzle matches ldmatrix read path: (col16B) ^ ((row&7)*16).
    {
        for (int u = tid; u < 8192; u += NTHR) {
            int row = u >> 8, k4 = u & 255;
            float4 v = *(const float4*)(Whh + (size_t)(n0 + row) * H_ + k4 * 4);
            __nv_bfloat162 h01 = __floats2bfloat162_rn(v.x, v.y);
            __nv_bfloat162 h23 = __floats2bfloat162_rn(v.z, v.w);
            __nv_bfloat162 l01 = __floats2bfloat162_rn(
                v.x - __bfloat162float(h01.x), v.y - __bfloat162float(h01.y));
            __nv_bfloat162 l23 = __floats2bfloat162_rn(
                v.z - __bfloat162float(h23.x), v.w - __bfloat162float(h23.y));
            int so = row * 2048 + ((k4 * 8) ^ ((row & 7) * 16));
            uint2 hp; hp.x = *(uint32_t*)&h01; hp.y = *(uint32_t*)&h23;
            uint2 lp; lp.x = *(uint32_t*)&l01; lp.y = *(uint32_t*)&l23;
            *(uint2*)(sm + SM_WHH_HI + so) = hp;
            *(uint2*)(sm + SM_WHH_LO + so) = lp;
        }
        for (int u = tid; u < 2048; u += NTHR) {
            int row = u >> 6, k4 = u & 63;
            float4 v = *(const float4*)(Wih + (size_t)(n0 + row) * I_ + k4 * 4);
            __nv_bfloat162 h01 = __floats2bfloat162_rn(v.x, v.y);
            __nv_bfloat162 h23 = __floats2bfloat162_rn(v.z, v.w);
            __nv_bfloat162 l01 = __floats2bfloat162_rn(
                v.x - __bfloat162float(h01.x), v.y - __bfloat162float(h01.y));
            __nv_bfloat162 l23 = __floats2bfloat162_rn(
                v.z - __bfloat162float(h23.x), v.w - __bfloat162float(h23.y));
            int so = row * 512 + ((k4 * 8) ^ ((row & 7) * 16));
            uint2 hp; hp.x = *(uint32_t*)&h01; hp.y = *(uint32_t*)&h23;
            uint2 lp; lp.x = *(uint32_t*)&l01; lp.y = *(uint32_t*)&l23;
            *(uint2*)(sm + SM_WIH_HI + so) = hp;
            *(uint2*)(sm + SM_WIH_LO + so) = lp;
        }
        if (tid < 32)
            ((float*)(sm + SM_BIAS))[tid] = b_ih[n0 + tid] + b_hh[n0 + tid];
    }

    unsigned phase = 0;
    if (tid == 0) phase = ((volatile unsigned*)&g_bar_phase4[ctaM * 32])[0];
    __syncthreads();

    // Per-lane fragment address constants (proven in R7/R10)
    const int arow = (lid & 7) + ((lid >> 3) & 1) * 8;
    const int aka2 = ((lid >> 4) & 1) * 16;
    const int axor = (arow & 7) * 16;
    const uint32_t stage_base = smb + SM_ASTAGE + (uint32_t)stream * 32768;
    const uint32_t a_lane = stage_base + (uint32_t)(wm * 16 + arow) * 256;

    const int brow = wn * 16 + (lid & 7) + ((lid >> 4) & 1) * 8;
    const int bka2 = ((lid >> 3) & 1) * 16;
    const int bxor = (brow & 7) * 16;
    const uint32_t bhh_lane = smb + SM_WHH_HI + (uint32_t)brow * 2048;
    const uint32_t bih_lane = smb + SM_WIH_HI + (uint32_t)brow * 512;

    const int g  = lid >> 2;
    const int tg = lid & 3;

    for (int t = 0; t < T_; t++) {
        const char* hhi = (const char*)g_h_hi[t & 1];
        const char* hlo = (const char*)g_h_lo[t & 1];

        float acc[2][2][4];
        #pragma unroll
        for (int p = 0; p < 2; p++)
            #pragma unroll
            for (int n = 0; n < 2; n++)
                #pragma unroll
                for (int j = 0; j < 4; j++) acc[p][n][j] = 0.f;

        // Stream s handles chunks {s, s+2, ..., s+8} (5 chunks), 2 private stages.
        load_chunk(stage_base, stream, hhi, hlo, m0, t, stid);
        asm volatile("cp.async.commit_group;");

        #pragma unroll
        for (int i = 0; i < 5; i++) {
            asm volatile("cp.async.wait_group 0;");   // chunk i data in
            stream_bar(stream);   // data visible to all stream warps; all done mma(i-1)
            const int c = 2 * i + stream;
            if (i < 4) {          // prefetch next chunk into the now-free stage
                load_chunk(stage_base + (uint32_t)((i + 1) & 1) * 16384,
                           c + 2, hhi, hlo, m0, t, stid);
                asm volatile("cp.async.commit_group;");
            }

            const uint32_t a_base = a_lane + (uint32_t)(i & 1) * 16384;
            uint32_t b_base, b_dlo;
            int kb0;
            if (c < 8) { b_base = bhh_lane; b_dlo = 65536; kb0 = c * 256; }
            else       { b_base = bih_lane; b_dlo = 16384; kb0 = (c - 8) * 256; }

            #pragma unroll
            for (int kk = 0; kk < 8; kk++) {
                uint32_t ahi[4], alo[4], bh[4], bl[4];
                uint32_t ao = (uint32_t)((kk * 32 + aka2) ^ axor);
                ldsm_x4(ahi, a_base + ao);
                ldsm_x4(alo, a_base + 8192 + ao);
                uint32_t bo = (uint32_t)((kb0 + kk * 32 + bka2) ^ bxor);
                ldsm_x4(bh, b_base + bo);          // NON-trans: [n][k] row-major
                ldsm_x4(bl, b_base + b_dlo + bo);

                float* C0 = acc[kk & 1][0];
                float* C1 = acc[kk & 1][1];
                mma16816(C0, ahi, bh[0], bh[1]);   // Ahi*Bhi
                mma16816(C1, ahi, bh[2], bh[3]);
                mma16816(C0, ahi, bl[0], bl[1]);   // Ahi*Blo
                mma16816(C1, ahi, bl[2], bl[3]);
                mma16816(C0, alo, bh[0], bh[1]);   // Alo*Bhi
                mma16816(C1, alo, bh[2], bh[3]);
            }
        }
        stream_bar(stream);   // all stream warps done with stages before red reuse

        // ---- Epilogue: merge streams, +bias, tanh, split-bf16 store ----
        {
            float vs[2][4];
            #pragma unroll
            for (int nt = 0; nt < 2; nt++)
                #pragma unroll
                for (int j = 0; j < 4; j++)
                    vs[nt][j] = acc[0][nt][j] + acc[1][nt][j];

            float* red = (float*)(sm + SM_RED);   // stream1 stage area (now idle)
            if (stream == 1) {
                #pragma unroll
                for (int nt = 0; nt < 2; nt++) {
                    int nloc = wn * 16 + nt * 8 + tg * 2;
                    #pragma unroll
                    for (int rp = 0; rp < 2; rp++) {
                        int mloc = wm * 16 + g + rp * 8;
                        red[mloc * 32 + nloc]     = vs[nt][rp * 2 + 0];
                        red[mloc * 32 + nloc + 1] = vs[nt][rp * 2 + 1];
                    }
                }
            }
            __syncthreads();
            if (stream == 0) {
                __nv_bfloat16* __restrict__ ohi = g_h_hi[(t + 1) & 1];
                __nv_bfloat16* __restrict__ olo = g_h_lo[(t + 1) & 1];
                const float* bias = (const float*)(sm + SM_BIAS);
                const bool last = (t == T_ - 1);
                #pragma unroll
                for (int nt = 0; nt < 2; nt++) {
                    int nloc = wn * 16 + nt * 8 + tg * 2;
                    int ng = n0 + nloc;
                    float b0v = bias[nloc], b1v = bias[nloc + 1];
                    #pragma unroll
                    for (int rp = 0; rp < 2; rp++) {
                        int mloc = wm * 16 + g + rp * 8;
                        int mg = m0 + mloc;
                        float v0 = tanhf(vs[nt][rp * 2 + 0] + red[mloc * 32 + nloc] + b0v);
                        float v1 = tanhf(vs[nt][rp * 2 + 1] + red[mloc * 32 + nloc + 1] + b1v);
                        __nv_bfloat16 h0 = __float2bfloat16(v0);
                        __nv_bfloat16 h1 = __float2bfloat16(v1);
                        __nv_bfloat16 l0 = __float2bfloat16(v0 - __bfloat162float(h0));
                        __nv_bfloat16 l1 = __float2bfloat16(v1 - __bfloat162float(h1));
                        size_t idx = (size_t)mg * H_ + ng;
                        *(uint32_t*)(ohi + idx) =
                            ((uint32_t)*(uint16_t*)&h1 << 16) | *(uint16_t*)&h0;
                        *(uint32_t*)(olo + idx) =
                            ((uint32_t)*(uint16_t*)&l1 << 16) | *(uint16_t*)&l0;
                        if (last) {
                            float2 f2v; f2v.x = v0; f2v.y = v1;
                            *(float2*)(g_h32 + idx) = f2v;
                        }
                    }
                }
            }
        }

        __threadfence();   // h stores visible GPU-wide before barrier release
        group_barrier(ctaM, &phase);
    }
}

// ---------------------------------------------------------------------------
// fc epilogue: one block per batch; warp-per-output-column, lanes split K.
// Coalesced W_fc float4 loads (R10 version was 32-way strided -> 135us).
// ---------------------------------------------------------------------------
__global__ __launch_bounds__(256) void fc_kernel(
    const float* __restrict__ W_fc, const float* __restrict__ b_fc,
    float* __restrict__ out)
{
    __shared__ float4 hsv4[H_ / 4];
    const int b = blockIdx.x;
    const int tid = threadIdx.x;
    const int wid = tid >> 5;
    const int lid = tid & 31;

    hsv4[tid] = ((const float4*)(g_h32 + (size_t)b * H_))[tid];  // 256 thr x 16B = 4KB
    __syncthreads();

    // Each of 8 warps handles 32 output columns; lanes split K (coalesced).
    #pragma unroll 4
    for (int oi = 0; oi < 32; oi++) {
        const int o = wid * 32 + oi;
        const float4* __restrict__ w4 = (const float4*)(W_fc + (size_t)o * H_);
        float a0 = 0.f, a1 = 0.f;
        #pragma unroll
        for (int i = 0; i < 8; i++) {
            float4 w = w4[lid + i * 32];
            float4 h = hsv4[lid + i * 32];
            if (i & 1) a1 += w.x * h.x + w.y * h.y + w.z * h.z + w.w * h.w;
            else       a0 += w.x * h.x + w.y * h.y + w.z * h.z + w.w * h.w;
        }
        float acc = a0 + a1;
        #pragma unroll
        for (int off = 16; off > 0; off >>= 1)
            acc += __shfl_xor_sync(0xFFFFFFFFu, acc, off);
        if (lid == 0) out[(size_t)b * O_ + o] = acc + b_fc[o];
    }
}

__global__ void copy_hidden(float* __restrict__ dst)
{
    int idx = blockIdx.x * blockDim.x + threadIdx.x;
    if (idx < B_ * H_) dst[idx] = g_h32[idx];
}

// ---------------------------------------------------------------------------
extern "C" void kernel_launch(void* const* d_in, const int* in_sizes, int n_in,
                              void* d_out, int out_size)
{
    const float* x      = (const float*)d_in[0];
    const float* hidden = (const float*)d_in[1];
    const float* W_ih   = (const float*)d_in[2];
    const float* W_hh   = (const float*)d_in[3];
    const float* b_ih   = (const float*)d_in[4];
    const float* b_hh   = (const float*)d_in[5];
    const float* W_fc   = (const float*)d_in[6];
    const float* b_fc   = (const float*)d_in[7];
    float* out = (float*)d_out;

    cudaFuncSetAttribute(rnn_persistent, cudaFuncAttributeMaxDynamicSharedMemorySize,
                         SM_TOTAL);

    // Resolve device-global scratch addresses (host-side, not a stream op)
    static __nv_bfloat16 *p_xhi = nullptr, *p_xlo = nullptr,
                         *p_hhi = nullptr, *p_hlo = nullptr;
    if (!p_xhi) {
        cudaGetSymbolAddress((void**)&p_xhi, g_x_hi);
        cudaGetSymbolAddress((void**)&p_xlo, g_x_lo);
        cudaGetSymbolAddress((void**)&p_hhi, g_h_hi);
        cudaGetSymbolAddress((void**)&p_hlo, g_h_lo);
    }

    // 1) split x and initial hidden to bf16 hi/lo (W splits live in the prologue)
    split_pair<<<(B_ * T_ * I_ + 255) / 256, 256>>>(x, p_xhi, p_xlo, B_ * T_ * I_);
    split_pair<<<(B_ * H_ + 255) / 256, 256>>>(hidden, p_hhi, p_hlo, B_ * H_);

    // 2) full recurrence in ONE persistent launch
    rnn_persistent<<<NB, NTHR, SM_TOTAL>>>(b_ih, b_hh, W_hh, W_ih);

    // 3) fc epilogue + hidden output
    fc_kernel<<<B_, 256>>>(W_fc, b_fc, out);
    if (out_size >= B_ * O_ + B_ * H_)
        copy_hidden<<<(B_ * H_ + 255) / 256, 256>>>(out + B_ * O_);
}